// round 13
// baseline (speedup 1.0000x reference)
#include <cuda_runtime.h>
#include <cuda_bf16.h>
#include <cstdint>

#define B_ 64
#define S_ 512
#define E_ 256
#define H_ 1024
#define V_ 128

#define NCTA 64            // persistent CTAs (1/SM, all resident in wave 1)
#define TPB 256            // 8 warps
#define COLS 16            // hidden columns owned per CTA
#define PAIRS 512          // H/2 bf16x2 pairs per row
#define SLOT 65536         // words per h-slot: 64 rows x 1024 words
#define UST 1028           // smem words per U column (1024 + 4 pad -> conflict-free)
#define PF 4               // A-stream prefetch depth (register ring)

// Fragment-major word layout within a row (1024 words = 4KB):
//   word(row, it, pb, c) = row*1024 + it*16 + pb*4 + c
//   c: 0=hi(p), 1=lo(p), 2=hi(p+4), 3=lo(p+4)   with p = it*8 + pb

// ---------------- persistent device scratch ----------------
__device__ uint32_t g_hh[(S_ + 1) * SLOT];   // h_0..h_512 (hi/lo interleaved)
__device__ uint32_t g_rh[SLOT];              // r*h broadcast (per step)
__device__ uint32_t g_wfc[V_ * 1024];        // W_fc split, fragment-major
__device__ float    g_eproj[3][V_ * H_];     // embproj tables (r,z,h gates)
__device__ unsigned g_cnt;                   // global barrier counter

// ---------------- helpers ----------------
__device__ __forceinline__ void split2(float a, float b, uint32_t& whi, uint32_t& wlo) {
    __nv_bfloat16 ah = __float2bfloat16_rn(a);
    __nv_bfloat16 bh = __float2bfloat16_rn(b);
    float ar = a - __bfloat162float(ah);
    float br = b - __bfloat162float(bh);
    __nv_bfloat162 vh; vh.x = ah; vh.y = bh;
    __nv_bfloat162 vl; vl.x = __float2bfloat16_rn(ar); vl.y = __float2bfloat16_rn(br);
    whi = *reinterpret_cast<uint32_t*>(&vh);
    wlo = *reinterpret_cast<uint32_t*>(&vl);
}

__device__ __forceinline__ void mma16(float* c, uint32_t a0, uint32_t a1, uint32_t a2,
                                      uint32_t a3, uint32_t b0, uint32_t b1) {
    asm volatile(
        "mma.sync.aligned.m16n8k16.row.col.f32.bf16.bf16.f32 "
        "{%0,%1,%2,%3},{%4,%5,%6,%7},{%8,%9},{%0,%1,%2,%3};"
        : "+f"(c[0]), "+f"(c[1]), "+f"(c[2]), "+f"(c[3])
        : "r"(a0), "r"(a1), "r"(a2), "r"(a3), "r"(b0), "r"(b1));
}

// 3-term split mma: q0/q1 = (hi,lo,hi4,lo4) for rows r0/r1; b = (bh,bl,bh4,bl4)
__device__ __forceinline__ void mma3q(float* c, uint4 q0, uint4 q1, uint4 b) {
    mma16(c, q0.x, q1.x, q0.z, q1.z, b.x, b.z);   // Ahi*Bhi
    mma16(c, q0.y, q1.y, q0.w, q1.w, b.x, b.z);   // Alo*Bhi
    mma16(c, q0.x, q1.x, q0.z, q1.z, b.y, b.w);   // Ahi*Blo
}

// grid-wide barrier: all NCTA CTAs resident by construction.
// arrive: red.release (no return trip). poll: ld.acquire (no RMW serialization).
// post-sync __threadfence() emits CCTL.IVALL so cached loads see remote writes.
__device__ __forceinline__ void gbar(unsigned target) {
    __syncthreads();
    if (threadIdx.x == 0) {
        asm volatile("red.release.gpu.global.add.u32 [%0], %1;"
                     :: "l"(&g_cnt), "r"(1u) : "memory");
        unsigned v;
        do {
            asm volatile("ld.acquire.gpu.global.u32 %0, [%1];"
                         : "=r"(v) : "l"(&g_cnt) : "memory");
        } while (v < target);
    }
    __syncthreads();
    __threadfence();
}

// ---------------- init: zero h_0 slot, reset barrier counter ----------------
__global__ void k_init() {
    int i = blockIdx.x * blockDim.x + threadIdx.x;   // 16384 threads x uint4
    ((uint4*)g_hh)[i] = make_uint4(0u, 0u, 0u, 0u);  // 65536 words = slot 0
    if (i == 0) g_cnt = 0u;
}

// ---------------- W_fc split + repack to fragment-major ----------------
__global__ void k_wfcsplit(const float* __restrict__ Wfc) {
    int i = blockIdx.x * blockDim.x + threadIdx.x;   // 65536 pairs
    int v = i >> 9, p = i & 511;
    float2 val = ((const float2*)Wfc)[i];
    uint32_t hi, lo;
    split2(val.x, val.y, hi, lo);
    int w = v * 1024 + (p >> 3) * 16 + (p & 3) * 4 + 2 * ((p >> 2) & 1);
    g_wfc[w]     = hi;
    g_wfc[w + 1] = lo;
}

// ---------------- embproj: eproj[g][v][h] = emb[v,:] @ W_g[h,:]^T + 2*b_g[h] ----------------
__global__ void __launch_bounds__(256) k_embproj(const float* __restrict__ emb,
                                                 const float* __restrict__ Wr,
                                                 const float* __restrict__ Wz,
                                                 const float* __restrict__ Wh,
                                                 const float* __restrict__ br,
                                                 const float* __restrict__ bz,
                                                 const float* __restrict__ bh) {
    int wt   = (blockIdx.x * blockDim.x + threadIdx.x) >> 5;  // 0..3071
    int lane = threadIdx.x & 31;
    int g    = wt >> 10;
    int rem  = wt & 1023;
    int mi   = rem >> 7;    // 0..7   (16-row vocab tile)
    int ni   = rem & 127;   // 0..127 (8-col hidden tile)

    const float* W    = (g == 0) ? Wr : ((g == 1) ? Wz : Wh);
    const float* bias = (g == 0) ? br : ((g == 1) ? bz : bh);

    int r0 = 16 * mi + (lane >> 2), r1 = r0 + 8;
    int pb = lane & 3;
    const float* pA0 = emb + r0 * E_ + 2 * pb;
    const float* pA1 = emb + r1 * E_ + 2 * pb;
    const float* pB  = W + (8 * ni + (lane >> 2)) * E_ + 2 * pb;

    float acc[4] = {0.f, 0.f, 0.f, 0.f};
#pragma unroll
    for (int kp = 0; kp < E_ / 2; kp += 8) {    // 16 iters of k16
        float2 va0 = *(const float2*)(pA0 + 2 * kp);
        float2 va2 = *(const float2*)(pA0 + 2 * kp + 8);
        float2 va1 = *(const float2*)(pA1 + 2 * kp);
        float2 va3 = *(const float2*)(pA1 + 2 * kp + 8);
        uint4 q0, q1;
        split2(va0.x, va0.y, q0.x, q0.y);
        split2(va2.x, va2.y, q0.z, q0.w);
        split2(va1.x, va1.y, q1.x, q1.y);
        split2(va3.x, va3.y, q1.z, q1.w);
        float2 vb0 = *(const float2*)(pB + 2 * kp);
        float2 vb1 = *(const float2*)(pB + 2 * kp + 8);
        uint4 b;
        split2(vb0.x, vb0.y, b.x, b.y);
        split2(vb1.x, vb1.y, b.z, b.w);
        mma3q(acc, q0, q1, b);
    }
#pragma unroll
    for (int i = 0; i < 4; i++) {
        int row = (i >= 2) ? r1 : r0;
        int col = 8 * ni + 2 * pb + (i & 1);
        g_eproj[g][row * H_ + col] = acc[i] + 2.0f * bias[col];
    }
}

// ---------------- persistent GRU recurrence ----------------
__global__ void __launch_bounds__(TPB, 1) k_gru(const int* __restrict__ x,
                                                const float* __restrict__ Ur,
                                                const float* __restrict__ Uz,
                                                const float* __restrict__ Uh) {
    extern __shared__ uint32_t smw[];
    const int GATEW = COLS * UST;     // 16448 words per gate
    int tid = threadIdx.x;
    int cta = blockIdx.x;
    int c0  = cta * COLS;

    // load + split + repack this CTA's U slices into SMEM (fragment-major)
    for (int g = 0; g < 3; g++) {
        const float* U = (g == 0) ? Ur : ((g == 1) ? Uz : Uh);
        uint32_t* dst = smw + g * GATEW;
        for (int i = tid; i < COLS * PAIRS; i += TPB) {
            int c = i >> 9, p = i & 511;
            float2 v = *(const float2*)(U + (size_t)(c0 + c) * H_ + 2 * p);
            uint32_t hi, lo;
            split2(v.x, v.y, hi, lo);
            int w = c * UST + (p >> 3) * 16 + (p & 3) * 4 + 2 * ((p >> 2) & 1);
            dst[w]     = hi;
            dst[w + 1] = lo;
        }
    }
    __syncthreads();

    int w = tid >> 5, lane = tid & 31;
    int mi = w >> 1, ni = w & 1;                 // 4 m-tiles x 2 n-tiles
    int r0 = 16 * mi + (lane >> 2), r1 = r0 + 8;
    int pb = lane & 3;

    int brow = (8 * ni + (lane >> 2)) * UST + pb * 4;
    const uint32_t* pBr = smw + brow;
    const uint32_t* pBz = smw + GATEW + brow;
    const uint32_t* pBh = smw + 2 * GATEW + brow;

    int aoff0 = r0 * 1024 + pb * 4;
    int aoff1 = r1 * 1024 + pb * 4;

    int colBase = c0 + 8 * ni + 2 * pb;          // even
    int pidx = colBase >> 1;                     // pair index 0..511
    int eoff = (pidx >> 3) * 16 + (pidx & 3) * 4 + 2 * ((pidx >> 2) & 1);
    int woff0 = r0 * 1024 + eoff;
    int woff1 = r1 * 1024 + eoff;

    float h_own[4] = {0.f, 0.f, 0.f, 0.f};       // this thread's 4 h values
    unsigned target = 0;

    for (int t = 0; t < S_; ++t) {
        const uint32_t* pA0 = g_hh + (size_t)t * SLOT + aoff0;
        const uint32_t* pA1 = g_hh + (size_t)t * SLOT + aoff1;

        // token + ALL input-projection gathers up front (xh overlaps barrier wait)
        int tok0 = x[r0 * S_ + t];
        int tok1 = x[r1 * S_ + t];
        float xr[4], xz[4], xh[4];
#pragma unroll
        for (int i = 0; i < 4; i++) {
            int tok = (i >= 2) ? tok1 : tok0;
            int col = colBase + (i & 1);
            xr[i] = g_eproj[0][tok * H_ + col];
            xz[i] = g_eproj[1][tok * H_ + col];
            xh[i] = g_eproj[2][tok * H_ + col];
        }

        // ---- phase 1: r,z gates (depth-PF register-ring prefetch on A) ----
        float accR[4] = {0.f, 0.f, 0.f, 0.f};
        float accZ[4] = {0.f, 0.f, 0.f, 0.f};
        uint4 a0s[PF], a1s[PF];
#pragma unroll
        for (int d = 0; d < PF; d++) {
            a0s[d] = *(const uint4*)(pA0 + d * 16);
            a1s[d] = *(const uint4*)(pA1 + d * 16);
        }
#pragma unroll 4
        for (int it = 0; it < 64 - PF; ++it) {
            int sl = it & (PF - 1);
            uint4 a0 = a0s[sl], a1 = a1s[sl];
            a0s[sl] = *(const uint4*)(pA0 + (it + PF) * 16);
            a1s[sl] = *(const uint4*)(pA1 + (it + PF) * 16);
            uint4 brv = *(const uint4*)(pBr + it * 16);
            uint4 bzv = *(const uint4*)(pBz + it * 16);
            mma3q(accR, a0, a1, brv);
            mma3q(accZ, a0, a1, bzv);
        }
#pragma unroll
        for (int it = 64 - PF; it < 64; ++it) {
            int sl = it & (PF - 1);
            uint4 brv = *(const uint4*)(pBr + it * 16);
            uint4 bzv = *(const uint4*)(pBz + it * 16);
            mma3q(accR, a0s[sl], a1s[sl], brv);
            mma3q(accZ, a0s[sl], a1s[sl], bzv);
        }

        float zv[4], rh[4];
#pragma unroll
        for (int i = 0; i < 4; i++) {
            float rg = 1.f / (1.f + __expf(-(accR[i] + xr[i])));
            zv[i]    = 1.f / (1.f + __expf(-(accZ[i] + xz[i])));
            rh[i]    = rg * h_own[i];
        }
        {
            uint32_t hi, lo;
            split2(rh[0], rh[1], hi, lo);
            *(uint2*)(g_rh + woff0) = make_uint2(hi, lo);
            split2(rh[2], rh[3], hi, lo);
            *(uint2*)(g_rh + woff1) = make_uint2(hi, lo);
        }
        target += NCTA;
        gbar(target);

        // ---- phase 2: candidate h, state update ----
        float accH[4] = {0.f, 0.f, 0.f, 0.f};
        const uint32_t* qA0 = g_rh + aoff0;
        const uint32_t* qA1 = g_rh + aoff1;
#pragma unroll
        for (int d = 0; d < PF; d++) {
            a0s[d] = *(const uint4*)(qA0 + d * 16);
            a1s[d] = *(const uint4*)(qA1 + d * 16);
        }
#pragma unroll 4
        for (int it = 0; it < 64 - PF; ++it) {
            int sl = it & (PF - 1);
            uint4 a0 = a0s[sl], a1 = a1s[sl];
            a0s[sl] = *(const uint4*)(qA0 + (it + PF) * 16);
            a1s[sl] = *(const uint4*)(qA1 + (it + PF) * 16);
            uint4 bhv = *(const uint4*)(pBh + it * 16);
            mma3q(accH, a0, a1, bhv);
        }
#pragma unroll
        for (int it = 64 - PF; it < 64; ++it) {
            int sl = it & (PF - 1);
            uint4 bhv = *(const uint4*)(pBh + it * 16);
            mma3q(accH, a0s[sl], a1s[sl], bhv);
        }

        uint32_t* nh = g_hh + (size_t)(t + 1) * SLOT;
#pragma unroll
        for (int i = 0; i < 4; i++) {
            float ht = tanhf(accH[i] + xh[i]);
            h_own[i] = (1.f - zv[i]) * ht + zv[i] * h_own[i];
        }
        {
            uint32_t hi, lo;
            split2(h_own[0], h_own[1], hi, lo);
            *(uint2*)(nh + woff0) = make_uint2(hi, lo);
            split2(h_own[2], h_own[3], hi, lo);
            *(uint2*)(nh + woff1) = make_uint2(hi, lo);
        }
        target += NCTA;
        gbar(target);
    }
}

// ---------------- logits: [32768,1024] @ [1024,128]^T + b_fc ----------------
__global__ void __launch_bounds__(256) k_logits(const float* __restrict__ bfc,
                                                float* __restrict__ out) {
    int w = threadIdx.x >> 5, lane = threadIdx.x & 31;
    int rowTile = blockIdx.x * 8 + w;                 // 0..2047
    int r0 = rowTile * 16 + (lane >> 2), r1 = r0 + 8; // same seq position block
    int pb = lane & 3;

    int s  = r0 >> 6;
    int b0 = r0 & 63, b1 = r1 & 63;
    const uint32_t* base = g_hh + (size_t)(s + 1) * SLOT;
    const uint32_t* pA0 = base + b0 * 1024 + pb * 4;
    const uint32_t* pA1 = base + b1 * 1024 + pb * 4;
    const uint32_t* pB  = g_wfc + (lane >> 2) * 1024 + pb * 4;

    float acc[16][4];
#pragma unroll
    for (int nt = 0; nt < 16; nt++)
#pragma unroll
        for (int i = 0; i < 4; i++) acc[nt][i] = 0.f;

    for (int it = 0; it < 64; ++it) {
        uint4 q0 = *(const uint4*)(pA0 + it * 16);
        uint4 q1 = *(const uint4*)(pA1 + it * 16);
#pragma unroll
        for (int nt = 0; nt < 16; nt++) {
            uint4 b = *(const uint4*)(pB + nt * 8 * 1024 + it * 16);
            mma3q(acc[nt], q0, q1, b);
        }
    }
#pragma unroll
    for (int nt = 0; nt < 16; nt++)
#pragma unroll
        for (int i = 0; i < 4; i++) {
            int row = (i >= 2) ? r1 : r0;
            int v   = nt * 8 + 2 * pb + (i & 1);
            int ss  = row >> 6;
            int bb  = row & 63;
            out[bb * (S_ * V_) + ss * V_ + v] = acc[nt][i] + bfc[v];
        }
}

// ---------------- h_last: reconstruct fp32 from slot 512 ----------------
__global__ void k_hlast(float* __restrict__ out) {
    int i = blockIdx.x * blockDim.x + threadIdx.x;    // 32768 pairs
    int b = i >> 9, p = i & 511;
    int wrd = S_ * SLOT + b * 1024 + (p >> 3) * 16 + (p & 3) * 4 + 2 * ((p >> 2) & 1);
    uint2 v = *(const uint2*)(g_hh + wrd);
    __nv_bfloat162 vh = *reinterpret_cast<__nv_bfloat162*>(&v.x);
    __nv_bfloat162 vl = *reinterpret_cast<__nv_bfloat162*>(&v.y);
    float* o = out + (size_t)B_ * S_ * V_ + b * H_ + 2 * p;
    o[0] = __bfloat162float(vh.x) + __bfloat162float(vl.x);
    o[1] = __bfloat162float(vh.y) + __bfloat162float(vl.y);
}

// ---------------- launch ----------------
extern "C" void kernel_launch(void* const* d_in, const int* in_sizes, int n_in,
                              void* d_out, int out_size) {
    const int*   x   = (const int*)d_in[0];
    const float* emb = (const float*)d_in[1];
    const float* Wr  = (const float*)d_in[2];
    const float* Ur  = (const float*)d_in[3];
    const float* br  = (const float*)d_in[4];
    const float* Wz  = (const float*)d_in[5];
    const float* Uz  = (const float*)d_in[6];
    const float* bz  = (const float*)d_in[7];
    const float* Wh  = (const float*)d_in[8];
    const float* Uh  = (const float*)d_in[9];
    const float* bh  = (const float*)d_in[10];
    const float* Wfc = (const float*)d_in[11];
    const float* bfc = (const float*)d_in[12];
    float* out = (float*)d_out;

    const int smem_bytes = 3 * COLS * UST * 4;  // 197376 B
    cudaFuncSetAttribute(k_gru, cudaFuncAttributeMaxDynamicSharedMemorySize,
                         smem_bytes);

    k_init<<<64, 256>>>();
    k_wfcsplit<<<256, 256>>>(Wfc);
    k_embproj<<<384, 256>>>(emb, Wr, Wz, Wh, br, bz, bh);
    k_gru<<<NCTA, TPB, smem_bytes>>>(x, Ur, Uz, Uh);
    k_logits<<<256, 256>>>(bfc, out);
    if (out_size >= B_ * S_ * V_ + B_ * H_) {
        k_hlast<<<128, 256>>>(out);
    }
}

// round 14
// speedup vs baseline: 1.0312x; 1.0312x over previous
#include <cuda_runtime.h>
#include <cuda_bf16.h>
#include <cstdint>

#define B_ 64
#define S_ 512
#define E_ 256
#define H_ 1024
#define V_ 128

#define NCTA 64            // persistent CTAs (1/SM, all resident in wave 1)
#define TPB 512            // 16 warps: 8 tiles x 2 K-halves
#define COLS 16            // hidden columns owned per CTA
#define PAIRS 512          // H/2 bf16x2 pairs per row
#define SLOT 65536         // words per h-slot: 64 rows x 1024 words
#define UST 1028           // smem words per U column (1024 + 4 pad -> conflict-free)

// Fragment-major word layout within a row (1024 words = 4KB):
//   word(row, it, pb, c) = row*1024 + it*16 + pb*4 + c
//   c: 0=hi(p), 1=lo(p), 2=hi(p+4), 3=lo(p+4)   with p = it*8 + pb

// ---------------- persistent device scratch ----------------
__device__ uint32_t g_hh[(S_ + 1) * SLOT];   // h_0..h_512 (hi/lo interleaved)
__device__ uint32_t g_rh[SLOT];              // r*h broadcast (per step)
__device__ uint32_t g_wfc[V_ * 1024];        // W_fc split, fragment-major
__device__ float    g_eproj[3][V_ * H_];     // embproj tables (r,z,h gates)
__device__ unsigned g_cnt;                   // global barrier counter

// ---------------- helpers ----------------
__device__ __forceinline__ void split2(float a, float b, uint32_t& whi, uint32_t& wlo) {
    __nv_bfloat16 ah = __float2bfloat16_rn(a);
    __nv_bfloat16 bh = __float2bfloat16_rn(b);
    float ar = a - __bfloat162float(ah);
    float br = b - __bfloat162float(bh);
    __nv_bfloat162 vh; vh.x = ah; vh.y = bh;
    __nv_bfloat162 vl; vl.x = __float2bfloat16_rn(ar); vl.y = __float2bfloat16_rn(br);
    whi = *reinterpret_cast<uint32_t*>(&vh);
    wlo = *reinterpret_cast<uint32_t*>(&vl);
}

__device__ __forceinline__ void mma16(float* c, uint32_t a0, uint32_t a1, uint32_t a2,
                                      uint32_t a3, uint32_t b0, uint32_t b1) {
    asm volatile(
        "mma.sync.aligned.m16n8k16.row.col.f32.bf16.bf16.f32 "
        "{%0,%1,%2,%3},{%4,%5,%6,%7},{%8,%9},{%0,%1,%2,%3};"
        : "+f"(c[0]), "+f"(c[1]), "+f"(c[2]), "+f"(c[3])
        : "r"(a0), "r"(a1), "r"(a2), "r"(a3), "r"(b0), "r"(b1));
}

// 3-term split mma: q0/q1 = (hi,lo,hi4,lo4) for rows r0/r1; b = (bh,bl,bh4,bl4)
__device__ __forceinline__ void mma3q(float* c, uint4 q0, uint4 q1, uint4 b) {
    mma16(c, q0.x, q1.x, q0.z, q1.z, b.x, b.z);   // Ahi*Bhi
    mma16(c, q0.y, q1.y, q0.w, q1.w, b.x, b.z);   // Alo*Bhi
    mma16(c, q0.x, q1.x, q0.z, q1.z, b.y, b.w);   // Ahi*Blo
}

// grid-wide barrier: all NCTA CTAs resident by construction.
__device__ __forceinline__ void gbar(unsigned target) {
    __syncthreads();
    if (threadIdx.x == 0) {
        asm volatile("red.release.gpu.global.add.u32 [%0], %1;"
                     :: "l"(&g_cnt), "r"(1u) : "memory");
        unsigned v;
        do {
            asm volatile("ld.acquire.gpu.global.u32 %0, [%1];"
                         : "=r"(v) : "l"(&g_cnt) : "memory");
        } while (v < target);
    }
    __syncthreads();
    __threadfence();
}

// ---------------- init: zero h_0 slot, reset barrier counter ----------------
__global__ void k_init() {
    int i = blockIdx.x * blockDim.x + threadIdx.x;   // 16384 threads x uint4
    ((uint4*)g_hh)[i] = make_uint4(0u, 0u, 0u, 0u);  // 65536 words = slot 0
    if (i == 0) g_cnt = 0u;
}

// ---------------- W_fc split + repack to fragment-major ----------------
__global__ void k_wfcsplit(const float* __restrict__ Wfc) {
    int i = blockIdx.x * blockDim.x + threadIdx.x;   // 65536 pairs
    int v = i >> 9, p = i & 511;
    float2 val = ((const float2*)Wfc)[i];
    uint32_t hi, lo;
    split2(val.x, val.y, hi, lo);
    int w = v * 1024 + (p >> 3) * 16 + (p & 3) * 4 + 2 * ((p >> 2) & 1);
    g_wfc[w]     = hi;
    g_wfc[w + 1] = lo;
}

// ---------------- embproj: eproj[g][v][h] = emb[v,:] @ W_g[h,:]^T + 2*b_g[h] ----------------
__global__ void __launch_bounds__(256) k_embproj(const float* __restrict__ emb,
                                                 const float* __restrict__ Wr,
                                                 const float* __restrict__ Wz,
                                                 const float* __restrict__ Wh,
                                                 const float* __restrict__ br,
                                                 const float* __restrict__ bz,
                                                 const float* __restrict__ bh) {
    int wt   = (blockIdx.x * blockDim.x + threadIdx.x) >> 5;  // 0..3071
    int lane = threadIdx.x & 31;
    int g    = wt >> 10;
    int rem  = wt & 1023;
    int mi   = rem >> 7;    // 0..7   (16-row vocab tile)
    int ni   = rem & 127;   // 0..127 (8-col hidden tile)

    const float* W    = (g == 0) ? Wr : ((g == 1) ? Wz : Wh);
    const float* bias = (g == 0) ? br : ((g == 1) ? bz : bh);

    int r0 = 16 * mi + (lane >> 2), r1 = r0 + 8;
    int pb = lane & 3;
    const float* pA0 = emb + r0 * E_ + 2 * pb;
    const float* pA1 = emb + r1 * E_ + 2 * pb;
    const float* pB  = W + (8 * ni + (lane >> 2)) * E_ + 2 * pb;

    float acc[4] = {0.f, 0.f, 0.f, 0.f};
#pragma unroll
    for (int kp = 0; kp < E_ / 2; kp += 8) {    // 16 iters of k16
        float2 va0 = *(const float2*)(pA0 + 2 * kp);
        float2 va2 = *(const float2*)(pA0 + 2 * kp + 8);
        float2 va1 = *(const float2*)(pA1 + 2 * kp);
        float2 va3 = *(const float2*)(pA1 + 2 * kp + 8);
        uint4 q0, q1;
        split2(va0.x, va0.y, q0.x, q0.y);
        split2(va2.x, va2.y, q0.z, q0.w);
        split2(va1.x, va1.y, q1.x, q1.y);
        split2(va3.x, va3.y, q1.z, q1.w);
        float2 vb0 = *(const float2*)(pB + 2 * kp);
        float2 vb1 = *(const float2*)(pB + 2 * kp + 8);
        uint4 b;
        split2(vb0.x, vb0.y, b.x, b.y);
        split2(vb1.x, vb1.y, b.z, b.w);
        mma3q(acc, q0, q1, b);
    }
#pragma unroll
    for (int i = 0; i < 4; i++) {
        int row = (i >= 2) ? r1 : r0;
        int col = 8 * ni + 2 * pb + (i & 1);
        g_eproj[g][row * H_ + col] = acc[i] + 2.0f * bias[col];
    }
}

// ---------------- persistent GRU recurrence (16 warps: 8 tiles x 2 K-halves) ----------------
__global__ void __launch_bounds__(TPB, 1) k_gru(const int* __restrict__ x,
                                                const float* __restrict__ Ur,
                                                const float* __restrict__ Uz,
                                                const float* __restrict__ Uh) {
    extern __shared__ uint32_t smw[];
    const int GATEW = COLS * UST;     // 16448 words per gate
    float* red = (float*)(smw + 3 * GATEW);   // 8 x 256 floats reduction buffer
    int tid = threadIdx.x;
    int cta = blockIdx.x;
    int c0  = cta * COLS;

    // load + split + repack this CTA's U slices into SMEM (fragment-major)
    for (int g = 0; g < 3; g++) {
        const float* U = (g == 0) ? Ur : ((g == 1) ? Uz : Uh);
        uint32_t* dst = smw + g * GATEW;
        for (int i = tid; i < COLS * PAIRS; i += TPB) {
            int c = i >> 9, p = i & 511;
            float2 v = *(const float2*)(U + (size_t)(c0 + c) * H_ + 2 * p);
            uint32_t hi, lo;
            split2(v.x, v.y, hi, lo);
            int w = c * UST + (p >> 3) * 16 + (p & 3) * 4 + 2 * ((p >> 2) & 1);
            dst[w]     = hi;
            dst[w + 1] = lo;
        }
    }
    __syncthreads();

    int w  = tid >> 5, lane = tid & 31;
    int kh = w >> 3;                 // K-half: 0 or 1
    int wl = w & 7;                  // tile id 0..7
    int mi = wl >> 1, ni = wl & 1;   // 4 m-tiles x 2 n-tiles
    int r0 = 16 * mi + (lane >> 2), r1 = r0 + 8;
    int pb = lane & 3;
    int itBase = kh * 32;            // this warp's K range: [itBase, itBase+32)
    int rtid = (wl << 5) | lane;     // matching thread index in the OTHER K-half

    int brow = (8 * ni + (lane >> 2)) * UST + pb * 4 + itBase * 16;
    const uint32_t* pBr = smw + brow;
    const uint32_t* pBz = smw + GATEW + brow;
    const uint32_t* pBh = smw + 2 * GATEW + brow;

    int aoff0 = r0 * 1024 + pb * 4 + itBase * 16;
    int aoff1 = r1 * 1024 + pb * 4 + itBase * 16;

    int colBase = c0 + 8 * ni + 2 * pb;          // even
    int pidx = colBase >> 1;                     // pair index 0..511
    int eoff = (pidx >> 3) * 16 + (pidx & 3) * 4 + 2 * ((pidx >> 2) & 1);
    int woff0 = r0 * 1024 + eoff;
    int woff1 = r1 * 1024 + eoff;

    float h_own[4] = {0.f, 0.f, 0.f, 0.f};       // kh==0 threads own 4 h values
    unsigned target = 0;

    for (int t = 0; t < S_; ++t) {
        const uint32_t* pA0 = g_hh + (size_t)t * SLOT + aoff0;
        const uint32_t* pA1 = g_hh + (size_t)t * SLOT + aoff1;

        // token + input-projection gathers (only the epilogue half needs them)
        int tok0 = 0, tok1 = 0;
        float xr[4], xz[4], xh[4];
        if (kh == 0) {
            tok0 = x[r0 * S_ + t];
            tok1 = x[r1 * S_ + t];
#pragma unroll
            for (int i = 0; i < 4; i++) {
                int tok = (i >= 2) ? tok1 : tok0;
                int col = colBase + (i & 1);
                xr[i] = g_eproj[0][tok * H_ + col];
                xz[i] = g_eproj[1][tok * H_ + col];
                xh[i] = g_eproj[2][tok * H_ + col];
            }
        }

        // ---- phase 1: r,z gate partials over this warp's K half ----
        float accR[4] = {0.f, 0.f, 0.f, 0.f};
        float accZ[4] = {0.f, 0.f, 0.f, 0.f};
        uint4 a0 = *(const uint4*)pA0;
        uint4 a1 = *(const uint4*)pA1;
#pragma unroll 4
        for (int it = 0; it < 31; ++it) {
            uint4 n0 = *(const uint4*)(pA0 + (it + 1) * 16);
            uint4 n1 = *(const uint4*)(pA1 + (it + 1) * 16);
            uint4 brv = *(const uint4*)(pBr + it * 16);
            uint4 bzv = *(const uint4*)(pBz + it * 16);
            mma3q(accR, a0, a1, brv);
            mma3q(accZ, a0, a1, bzv);
            a0 = n0; a1 = n1;
        }
        {
            uint4 brv = *(const uint4*)(pBr + 31 * 16);
            uint4 bzv = *(const uint4*)(pBz + 31 * 16);
            mma3q(accR, a0, a1, brv);
            mma3q(accZ, a0, a1, bzv);
        }

        if (kh == 1) {
#pragma unroll
            for (int i = 0; i < 4; i++) {
                red[i * 256 + rtid]       = accR[i];
                red[(4 + i) * 256 + rtid] = accZ[i];
            }
        }
        __syncthreads();

        float zv[4];
        if (kh == 0) {
            float rh[4];
#pragma unroll
            for (int i = 0; i < 4; i++) {
                float aR = accR[i] + red[i * 256 + rtid];
                float aZ = accZ[i] + red[(4 + i) * 256 + rtid];
                float rg = 1.f / (1.f + __expf(-(aR + xr[i])));
                zv[i]    = 1.f / (1.f + __expf(-(aZ + xz[i])));
                rh[i]    = rg * h_own[i];
            }
            uint32_t hi, lo;
            split2(rh[0], rh[1], hi, lo);
            *(uint2*)(g_rh + woff0) = make_uint2(hi, lo);
            split2(rh[2], rh[3], hi, lo);
            *(uint2*)(g_rh + woff1) = make_uint2(hi, lo);
        }
        target += NCTA;
        gbar(target);

        // ---- phase 2: candidate h partials, state update ----
        float accH[4] = {0.f, 0.f, 0.f, 0.f};
        const uint32_t* qA0 = g_rh + aoff0;
        const uint32_t* qA1 = g_rh + aoff1;
        a0 = *(const uint4*)qA0;
        a1 = *(const uint4*)qA1;
#pragma unroll 4
        for (int it = 0; it < 31; ++it) {
            uint4 n0 = *(const uint4*)(qA0 + (it + 1) * 16);
            uint4 n1 = *(const uint4*)(qA1 + (it + 1) * 16);
            uint4 bhv = *(const uint4*)(pBh + it * 16);
            mma3q(accH, a0, a1, bhv);
            a0 = n0; a1 = n1;
        }
        {
            uint4 bhv = *(const uint4*)(pBh + 31 * 16);
            mma3q(accH, a0, a1, bhv);
        }

        if (kh == 1) {
#pragma unroll
            for (int i = 0; i < 4; i++)
                red[i * 256 + rtid] = accH[i];
        }
        __syncthreads();

        if (kh == 0) {
            uint32_t* nh = g_hh + (size_t)(t + 1) * SLOT;
#pragma unroll
            for (int i = 0; i < 4; i++) {
                float aH = accH[i] + red[i * 256 + rtid];
                float ht = tanhf(aH + xh[i]);
                h_own[i] = (1.f - zv[i]) * ht + zv[i] * h_own[i];
            }
            uint32_t hi, lo;
            split2(h_own[0], h_own[1], hi, lo);
            *(uint2*)(nh + woff0) = make_uint2(hi, lo);
            split2(h_own[2], h_own[3], hi, lo);
            *(uint2*)(nh + woff1) = make_uint2(hi, lo);
        }
        target += NCTA;
        gbar(target);
    }
}

// ---------------- logits: [32768,1024] @ [1024,128]^T + b_fc ----------------
__global__ void __launch_bounds__(256) k_logits(const float* __restrict__ bfc,
                                                float* __restrict__ out) {
    int w = threadIdx.x >> 5, lane = threadIdx.x & 31;
    int rowTile = blockIdx.x * 8 + w;                 // 0..2047
    int r0 = rowTile * 16 + (lane >> 2), r1 = r0 + 8; // same seq position block
    int pb = lane & 3;

    int s  = r0 >> 6;
    int b0 = r0 & 63, b1 = r1 & 63;
    const uint32_t* base = g_hh + (size_t)(s + 1) * SLOT;
    const uint32_t* pA0 = base + b0 * 1024 + pb * 4;
    const uint32_t* pA1 = base + b1 * 1024 + pb * 4;
    const uint32_t* pB  = g_wfc + (lane >> 2) * 1024 + pb * 4;

    float acc[16][4];
#pragma unroll
    for (int nt = 0; nt < 16; nt++)
#pragma unroll
        for (int i = 0; i < 4; i++) acc[nt][i] = 0.f;

    for (int it = 0; it < 64; ++it) {
        uint4 q0 = *(const uint4*)(pA0 + it * 16);
        uint4 q1 = *(const uint4*)(pA1 + it * 16);
#pragma unroll
        for (int nt = 0; nt < 16; nt++) {
            uint4 b = *(const uint4*)(pB + nt * 8 * 1024 + it * 16);
            mma3q(acc[nt], q0, q1, b);
        }
    }
#pragma unroll
    for (int nt = 0; nt < 16; nt++)
#pragma unroll
        for (int i = 0; i < 4; i++) {
            int row = (i >= 2) ? r1 : r0;
            int v   = nt * 8 + 2 * pb + (i & 1);
            int ss  = row >> 6;
            int bb  = row & 63;
            out[bb * (S_ * V_) + ss * V_ + v] = acc[nt][i] + bfc[v];
        }
}

// ---------------- h_last: reconstruct fp32 from slot 512 ----------------
__global__ void k_hlast(float* __restrict__ out) {
    int i = blockIdx.x * blockDim.x + threadIdx.x;    // 32768 pairs
    int b = i >> 9, p = i & 511;
    int wrd = S_ * SLOT + b * 1024 + (p >> 3) * 16 + (p & 3) * 4 + 2 * ((p >> 2) & 1);
    uint2 v = *(const uint2*)(g_hh + wrd);
    __nv_bfloat162 vh = *reinterpret_cast<__nv_bfloat162*>(&v.x);
    __nv_bfloat162 vl = *reinterpret_cast<__nv_bfloat162*>(&v.y);
    float* o = out + (size_t)B_ * S_ * V_ + b * H_ + 2 * p;
    o[0] = __bfloat162float(vh.x) + __bfloat162float(vl.x);
    o[1] = __bfloat162float(vh.y) + __bfloat162float(vl.y);
}

// ---------------- launch ----------------
extern "C" void kernel_launch(void* const* d_in, const int* in_sizes, int n_in,
                              void* d_out, int out_size) {
    const int*   x   = (const int*)d_in[0];
    const float* emb = (const float*)d_in[1];
    const float* Wr  = (const float*)d_in[2];
    const float* Ur  = (const float*)d_in[3];
    const float* br  = (const float*)d_in[4];
    const float* Wz  = (const float*)d_in[5];
    const float* Uz  = (const float*)d_in[6];
    const float* bz  = (const float*)d_in[7];
    const float* Wh  = (const float*)d_in[8];
    const float* Uh  = (const float*)d_in[9];
    const float* bh  = (const float*)d_in[10];
    const float* Wfc = (const float*)d_in[11];
    const float* bfc = (const float*)d_in[12];
    float* out = (float*)d_out;

    const int smem_bytes = 3 * COLS * UST * 4 + 8 * 256 * 4;  // 197376 + 8192 B
    cudaFuncSetAttribute(k_gru, cudaFuncAttributeMaxDynamicSharedMemorySize,
                         smem_bytes);

    k_init<<<64, 256>>>();
    k_wfcsplit<<<256, 256>>>(Wfc);
    k_embproj<<<384, 256>>>(emb, Wr, Wz, Wh, br, bz, bh);
    k_gru<<<NCTA, TPB, smem_bytes>>>(x, Ur, Uz, Uh);
    k_logits<<<256, 256>>>(bfc, out);
    if (out_size >= B_ * S_ * V_ + B_ * H_) {
        k_hlast<<<128, 256>>>(out);
    }
}

// round 15
// speedup vs baseline: 1.0813x; 1.0486x over previous
#include <cuda_runtime.h>
#include <cuda_bf16.h>
#include <cstdint>

#define B_ 64
#define S_ 512
#define E_ 256
#define H_ 1024
#define V_ 128

#define NCTA 64            // persistent CTAs (1/SM, all resident in wave 1)
#define TPB 512            // 16 warps: 8 tiles x 2 K-halves
#define COLS 16            // hidden columns owned per CTA
#define PAIRS 512          // H/2 bf16x2 pairs per row
#define SLOT 65536         // words per h-slot: 64 rows x 1024 words
#define UST 1028           // smem words per U column (1024 + 4 pad -> conflict-free)

// Fragment-major word layout within a row (1024 words = 4KB):
//   word(row, it, pb, c) = row*1024 + it*16 + pb*4 + c
//   c: 0=hi(p), 1=lo(p), 2=hi(p+4), 3=lo(p+4)   with p = it*8 + pb

// ---------------- persistent device scratch ----------------
__device__ uint32_t g_hh[(S_ + 1) * SLOT];   // h_0..h_512 (hi/lo interleaved)
__device__ uint32_t g_rh[SLOT];              // r*h broadcast (per step)
__device__ uint32_t g_wfc[V_ * 1024];        // W_fc split, fragment-major
__device__ float    g_eproj[3][V_ * H_];     // embproj tables (r,z,h gates)
__device__ unsigned g_cnt;                   // global barrier counter

// ---------------- helpers ----------------
__device__ __forceinline__ void split2(float a, float b, uint32_t& whi, uint32_t& wlo) {
    __nv_bfloat16 ah = __float2bfloat16_rn(a);
    __nv_bfloat16 bh = __float2bfloat16_rn(b);
    float ar = a - __bfloat162float(ah);
    float br = b - __bfloat162float(bh);
    __nv_bfloat162 vh; vh.x = ah; vh.y = bh;
    __nv_bfloat162 vl; vl.x = __float2bfloat16_rn(ar); vl.y = __float2bfloat16_rn(br);
    whi = *reinterpret_cast<uint32_t*>(&vh);
    wlo = *reinterpret_cast<uint32_t*>(&vl);
}

__device__ __forceinline__ void mma16(float* c, uint32_t a0, uint32_t a1, uint32_t a2,
                                      uint32_t a3, uint32_t b0, uint32_t b1) {
    asm volatile(
        "mma.sync.aligned.m16n8k16.row.col.f32.bf16.bf16.f32 "
        "{%0,%1,%2,%3},{%4,%5,%6,%7},{%8,%9},{%0,%1,%2,%3};"
        : "+f"(c[0]), "+f"(c[1]), "+f"(c[2]), "+f"(c[3])
        : "r"(a0), "r"(a1), "r"(a2), "r"(a3), "r"(b0), "r"(b1));
}

// 3-term split mma: q0/q1 = (hi,lo,hi4,lo4) for rows r0/r1; b = (bh,bl,bh4,bl4)
__device__ __forceinline__ void mma3q(float* c, uint4 q0, uint4 q1, uint4 b) {
    mma16(c, q0.x, q1.x, q0.z, q1.z, b.x, b.z);   // Ahi*Bhi
    mma16(c, q0.y, q1.y, q0.w, q1.w, b.x, b.z);   // Alo*Bhi
    mma16(c, q0.x, q1.x, q0.z, q1.z, b.y, b.w);   // Ahi*Blo
}

// grid-wide barrier, cooperative-groups style: all NCTA CTAs resident.
// Writers: weak stores -> __syncthreads -> thread0 red.release (release seq).
// Readers: thread0 ld.acquire observes final count => synchronizes-with ALL
// 64 releases (RMW release-sequence rule); __syncthreads extends the
// happens-before to every thread in the CTA (shared per-SM L1 is handled by
// the acquire). NO per-thread __threadfence needed (this was costing
// ~2 gpu-scope MEMBARs per warp per step).
__device__ __forceinline__ void gbar(unsigned target) {
    __syncthreads();
    if (threadIdx.x == 0) {
        asm volatile("red.release.gpu.global.add.u32 [%0], %1;"
                     :: "l"(&g_cnt), "r"(1u) : "memory");
        unsigned v;
        do {
            asm volatile("ld.acquire.gpu.global.u32 %0, [%1];"
                         : "=r"(v) : "l"(&g_cnt) : "memory");
        } while (v < target);
    }
    __syncthreads();
}

// ---------------- init: zero h_0 slot, reset barrier counter ----------------
__global__ void k_init() {
    int i = blockIdx.x * blockDim.x + threadIdx.x;   // 16384 threads x uint4
    ((uint4*)g_hh)[i] = make_uint4(0u, 0u, 0u, 0u);  // 65536 words = slot 0
    if (i == 0) g_cnt = 0u;
}

// ---------------- W_fc split + repack to fragment-major ----------------
__global__ void k_wfcsplit(const float* __restrict__ Wfc) {
    int i = blockIdx.x * blockDim.x + threadIdx.x;   // 65536 pairs
    int v = i >> 9, p = i & 511;
    float2 val = ((const float2*)Wfc)[i];
    uint32_t hi, lo;
    split2(val.x, val.y, hi, lo);
    int w = v * 1024 + (p >> 3) * 16 + (p & 3) * 4 + 2 * ((p >> 2) & 1);
    g_wfc[w]     = hi;
    g_wfc[w + 1] = lo;
}

// ---------------- embproj: eproj[g][v][h] = emb[v,:] @ W_g[h,:]^T + 2*b_g[h] ----------------
__global__ void __launch_bounds__(256) k_embproj(const float* __restrict__ emb,
                                                 const float* __restrict__ Wr,
                                                 const float* __restrict__ Wz,
                                                 const float* __restrict__ Wh,
                                                 const float* __restrict__ br,
                                                 const float* __restrict__ bz,
                                                 const float* __restrict__ bh) {
    int wt   = (blockIdx.x * blockDim.x + threadIdx.x) >> 5;  // 0..3071
    int lane = threadIdx.x & 31;
    int g    = wt >> 10;
    int rem  = wt & 1023;
    int mi   = rem >> 7;    // 0..7   (16-row vocab tile)
    int ni   = rem & 127;   // 0..127 (8-col hidden tile)

    const float* W    = (g == 0) ? Wr : ((g == 1) ? Wz : Wh);
    const float* bias = (g == 0) ? br : ((g == 1) ? bz : bh);

    int r0 = 16 * mi + (lane >> 2), r1 = r0 + 8;
    int pb = lane & 3;
    const float* pA0 = emb + r0 * E_ + 2 * pb;
    const float* pA1 = emb + r1 * E_ + 2 * pb;
    const float* pB  = W + (8 * ni + (lane >> 2)) * E_ + 2 * pb;

    float acc[4] = {0.f, 0.f, 0.f, 0.f};
#pragma unroll
    for (int kp = 0; kp < E_ / 2; kp += 8) {    // 16 iters of k16
        float2 va0 = *(const float2*)(pA0 + 2 * kp);
        float2 va2 = *(const float2*)(pA0 + 2 * kp + 8);
        float2 va1 = *(const float2*)(pA1 + 2 * kp);
        float2 va3 = *(const float2*)(pA1 + 2 * kp + 8);
        uint4 q0, q1;
        split2(va0.x, va0.y, q0.x, q0.y);
        split2(va2.x, va2.y, q0.z, q0.w);
        split2(va1.x, va1.y, q1.x, q1.y);
        split2(va3.x, va3.y, q1.z, q1.w);
        float2 vb0 = *(const float2*)(pB + 2 * kp);
        float2 vb1 = *(const float2*)(pB + 2 * kp + 8);
        uint4 b;
        split2(vb0.x, vb0.y, b.x, b.y);
        split2(vb1.x, vb1.y, b.z, b.w);
        mma3q(acc, q0, q1, b);
    }
#pragma unroll
    for (int i = 0; i < 4; i++) {
        int row = (i >= 2) ? r1 : r0;
        int col = 8 * ni + 2 * pb + (i & 1);
        g_eproj[g][row * H_ + col] = acc[i] + 2.0f * bias[col];
    }
}

// ---------------- persistent GRU recurrence (16 warps: 8 tiles x 2 K-halves) ----------------
__global__ void __launch_bounds__(TPB, 1) k_gru(const int* __restrict__ x,
                                                const float* __restrict__ Ur,
                                                const float* __restrict__ Uz,
                                                const float* __restrict__ Uh) {
    extern __shared__ uint32_t smw[];
    const int GATEW = COLS * UST;     // 16448 words per gate
    float* red = (float*)(smw + 3 * GATEW);   // 8 x 256 floats reduction buffer
    int tid = threadIdx.x;
    int cta = blockIdx.x;
    int c0  = cta * COLS;

    // load + split + repack this CTA's U slices into SMEM (fragment-major)
    for (int g = 0; g < 3; g++) {
        const float* U = (g == 0) ? Ur : ((g == 1) ? Uz : Uh);
        uint32_t* dst = smw + g * GATEW;
        for (int i = tid; i < COLS * PAIRS; i += TPB) {
            int c = i >> 9, p = i & 511;
            float2 v = *(const float2*)(U + (size_t)(c0 + c) * H_ + 2 * p);
            uint32_t hi, lo;
            split2(v.x, v.y, hi, lo);
            int w = c * UST + (p >> 3) * 16 + (p & 3) * 4 + 2 * ((p >> 2) & 1);
            dst[w]     = hi;
            dst[w + 1] = lo;
        }
    }
    __syncthreads();

    int w  = tid >> 5, lane = tid & 31;
    int kh = w >> 3;                 // K-half: 0 or 1
    int wl = w & 7;                  // tile id 0..7
    int mi = wl >> 1, ni = wl & 1;   // 4 m-tiles x 2 n-tiles
    int r0 = 16 * mi + (lane >> 2), r1 = r0 + 8;
    int pb = lane & 3;
    int itBase = kh * 32;            // this warp's K range: [itBase, itBase+32)
    int rtid = (wl << 5) | lane;     // matching thread index in the OTHER K-half

    int brow = (8 * ni + (lane >> 2)) * UST + pb * 4 + itBase * 16;
    const uint32_t* pBr = smw + brow;
    const uint32_t* pBz = smw + GATEW + brow;
    const uint32_t* pBh = smw + 2 * GATEW + brow;

    int aoff0 = r0 * 1024 + pb * 4 + itBase * 16;
    int aoff1 = r1 * 1024 + pb * 4 + itBase * 16;

    int colBase = c0 + 8 * ni + 2 * pb;          // even
    int pidx = colBase >> 1;                     // pair index 0..511
    int eoff = (pidx >> 3) * 16 + (pidx & 3) * 4 + 2 * ((pidx >> 2) & 1);
    int woff0 = r0 * 1024 + eoff;
    int woff1 = r1 * 1024 + eoff;

    float h_own[4] = {0.f, 0.f, 0.f, 0.f};       // kh==0 threads own 4 h values
    unsigned target = 0;

    // pre-gather step-0 token projections (off the critical path)
    float xr[4], xz[4], xh[4];
    if (kh == 0) {
        int tok0 = x[r0 * S_ + 0];
        int tok1 = x[r1 * S_ + 0];
#pragma unroll
        for (int i = 0; i < 4; i++) {
            int tok = (i >= 2) ? tok1 : tok0;
            int col = colBase + (i & 1);
            xr[i] = g_eproj[0][tok * H_ + col];
            xz[i] = g_eproj[1][tok * H_ + col];
            xh[i] = g_eproj[2][tok * H_ + col];
        }
    }

    for (int t = 0; t < S_; ++t) {
        const uint32_t* pA0 = g_hh + (size_t)t * SLOT + aoff0;
        const uint32_t* pA1 = g_hh + (size_t)t * SLOT + aoff1;

        // ---- phase 1: r,z gate partials over this warp's K half ----
        float accR[4] = {0.f, 0.f, 0.f, 0.f};
        float accZ[4] = {0.f, 0.f, 0.f, 0.f};
        uint4 a0 = *(const uint4*)pA0;
        uint4 a1 = *(const uint4*)pA1;
#pragma unroll 4
        for (int it = 0; it < 31; ++it) {
            uint4 n0 = *(const uint4*)(pA0 + (it + 1) * 16);
            uint4 n1 = *(const uint4*)(pA1 + (it + 1) * 16);
            uint4 brv = *(const uint4*)(pBr + it * 16);
            uint4 bzv = *(const uint4*)(pBz + it * 16);
            mma3q(accR, a0, a1, brv);
            mma3q(accZ, a0, a1, bzv);
            a0 = n0; a1 = n1;
        }
        {
            uint4 brv = *(const uint4*)(pBr + 31 * 16);
            uint4 bzv = *(const uint4*)(pBz + 31 * 16);
            mma3q(accR, a0, a1, brv);
            mma3q(accZ, a0, a1, bzv);
        }

        if (kh == 1) {
#pragma unroll
            for (int i = 0; i < 4; i++) {
                red[i * 256 + rtid]       = accR[i];
                red[(4 + i) * 256 + rtid] = accZ[i];
            }
        }
        __syncthreads();

        float zv[4];
        if (kh == 0) {
            float rh[4];
#pragma unroll
            for (int i = 0; i < 4; i++) {
                float aR = accR[i] + red[i * 256 + rtid];
                float aZ = accZ[i] + red[(4 + i) * 256 + rtid];
                float rg = 1.f / (1.f + __expf(-(aR + xr[i])));
                zv[i]    = 1.f / (1.f + __expf(-(aZ + xz[i])));
                rh[i]    = rg * h_own[i];
            }
            uint32_t hi, lo;
            split2(rh[0], rh[1], hi, lo);
            *(uint2*)(g_rh + woff0) = make_uint2(hi, lo);
            split2(rh[2], rh[3], hi, lo);
            *(uint2*)(g_rh + woff1) = make_uint2(hi, lo);
        }
        target += NCTA;
        gbar(target);

        // ---- phase 2: candidate h partials, state update ----
        float accH[4] = {0.f, 0.f, 0.f, 0.f};
        const uint32_t* qA0 = g_rh + aoff0;
        const uint32_t* qA1 = g_rh + aoff1;
        a0 = *(const uint4*)qA0;
        a1 = *(const uint4*)qA1;
#pragma unroll 4
        for (int it = 0; it < 31; ++it) {
            uint4 n0 = *(const uint4*)(qA0 + (it + 1) * 16);
            uint4 n1 = *(const uint4*)(qA1 + (it + 1) * 16);
            uint4 bhv = *(const uint4*)(pBh + it * 16);
            mma3q(accH, a0, a1, bhv);
            a0 = n0; a1 = n1;
        }
        {
            uint4 bhv = *(const uint4*)(pBh + 31 * 16);
            mma3q(accH, a0, a1, bhv);
        }

        if (kh == 1) {
#pragma unroll
            for (int i = 0; i < 4; i++)
                red[i * 256 + rtid] = accH[i];
        }
        __syncthreads();

        if (kh == 0) {
            uint32_t* nh = g_hh + (size_t)(t + 1) * SLOT;
#pragma unroll
            for (int i = 0; i < 4; i++) {
                float aH = accH[i] + red[i * 256 + rtid];
                float ht = tanhf(aH + xh[i]);
                h_own[i] = (1.f - zv[i]) * ht + zv[i] * h_own[i];
            }
            uint32_t hi, lo;
            split2(h_own[0], h_own[1], hi, lo);
            *(uint2*)(nh + woff0) = make_uint2(hi, lo);
            split2(h_own[2], h_own[3], hi, lo);
            *(uint2*)(nh + woff1) = make_uint2(hi, lo);

            // prefetch next step's token projections BEFORE the barrier so the
            // post-barrier critical path starts directly with A-stream loads
            if (t + 1 < S_) {
                int tok0 = x[r0 * S_ + t + 1];
                int tok1 = x[r1 * S_ + t + 1];
#pragma unroll
                for (int i = 0; i < 4; i++) {
                    int tok = (i >= 2) ? tok1 : tok0;
                    int col = colBase + (i & 1);
                    xr[i] = g_eproj[0][tok * H_ + col];
                    xz[i] = g_eproj[1][tok * H_ + col];
                    xh[i] = g_eproj[2][tok * H_ + col];
                }
            }
        }
        target += NCTA;
        gbar(target);
    }
}

// ---------------- logits: [32768,1024] @ [1024,128]^T + b_fc ----------------
__global__ void __launch_bounds__(256) k_logits(const float* __restrict__ bfc,
                                                float* __restrict__ out) {
    int w = threadIdx.x >> 5, lane = threadIdx.x & 31;
    int rowTile = blockIdx.x * 8 + w;                 // 0..2047
    int r0 = rowTile * 16 + (lane >> 2), r1 = r0 + 8; // same seq position block
    int pb = lane & 3;

    int s  = r0 >> 6;
    int b0 = r0 & 63, b1 = r1 & 63;
    const uint32_t* base = g_hh + (size_t)(s + 1) * SLOT;
    const uint32_t* pA0 = base + b0 * 1024 + pb * 4;
    const uint32_t* pA1 = base + b1 * 1024 + pb * 4;
    const uint32_t* pB  = g_wfc + (lane >> 2) * 1024 + pb * 4;

    float acc[16][4];
#pragma unroll
    for (int nt = 0; nt < 16; nt++)
#pragma unroll
        for (int i = 0; i < 4; i++) acc[nt][i] = 0.f;

    for (int it = 0; it < 64; ++it) {
        uint4 q0 = *(const uint4*)(pA0 + it * 16);
        uint4 q1 = *(const uint4*)(pA1 + it * 16);
#pragma unroll
        for (int nt = 0; nt < 16; nt++) {
            uint4 b = *(const uint4*)(pB + nt * 8 * 1024 + it * 16);
            mma3q(acc[nt], q0, q1, b);
        }
    }
#pragma unroll
    for (int nt = 0; nt < 16; nt++)
#pragma unroll
        for (int i = 0; i < 4; i++) {
            int row = (i >= 2) ? r1 : r0;
            int v   = nt * 8 + 2 * pb + (i & 1);
            int ss  = row >> 6;
            int bb  = row & 63;
            out[bb * (S_ * V_) + ss * V_ + v] = acc[nt][i] + bfc[v];
        }
}

// ---------------- h_last: reconstruct fp32 from slot 512 ----------------
__global__ void k_hlast(float* __restrict__ out) {
    int i = blockIdx.x * blockDim.x + threadIdx.x;    // 32768 pairs
    int b = i >> 9, p = i & 511;
    int wrd = S_ * SLOT + b * 1024 + (p >> 3) * 16 + (p & 3) * 4 + 2 * ((p >> 2) & 1);
    uint2 v = *(const uint2*)(g_hh + wrd);
    __nv_bfloat162 vh = *reinterpret_cast<__nv_bfloat162*>(&v.x);
    __nv_bfloat162 vl = *reinterpret_cast<__nv_bfloat162*>(&v.y);
    float* o = out + (size_t)B_ * S_ * V_ + b * H_ + 2 * p;
    o[0] = __bfloat162float(vh.x) + __bfloat162float(vl.x);
    o[1] = __bfloat162float(vh.y) + __bfloat162float(vl.y);
}

// ---------------- launch ----------------
extern "C" void kernel_launch(void* const* d_in, const int* in_sizes, int n_in,
                              void* d_out, int out_size) {
    const int*   x   = (const int*)d_in[0];
    const float* emb = (const float*)d_in[1];
    const float* Wr  = (const float*)d_in[2];
    const float* Ur  = (const float*)d_in[3];
    const float* br  = (const float*)d_in[4];
    const float* Wz  = (const float*)d_in[5];
    const float* Uz  = (const float*)d_in[6];
    const float* bz  = (const float*)d_in[7];
    const float* Wh  = (const float*)d_in[8];
    const float* Uh  = (const float*)d_in[9];
    const float* bh  = (const float*)d_in[10];
    const float* Wfc = (const float*)d_in[11];
    const float* bfc = (const float*)d_in[12];
    float* out = (float*)d_out;

    const int smem_bytes = 3 * COLS * UST * 4 + 8 * 256 * 4;  // 197376 + 8192 B
    cudaFuncSetAttribute(k_gru, cudaFuncAttributeMaxDynamicSharedMemorySize,
                         smem_bytes);

    k_init<<<64, 256>>>();
    k_wfcsplit<<<256, 256>>>(Wfc);
    k_embproj<<<384, 256>>>(emb, Wr, Wz, Wh, br, bz, bh);
    k_gru<<<NCTA, TPB, smem_bytes>>>(x, Ur, Uz, Uh);
    k_logits<<<256, 256>>>(bfc, out);
    if (out_size >= B_ * S_ * V_ + B_ * H_) {
        k_hlast<<<128, 256>>>(out);
    }
}